// round 6
// baseline (speedup 1.0000x reference)
#include <cuda_runtime.h>
#include <cuda_bf16.h>

#define NTHREADS 256

struct Params { const float* p[24]; };

// ---- scratch (static device globals; no allocation) ----
__device__ float g_keys   [64*64*128];
__device__ float g_queries[64*64*128];
__device__ float g_hk     [64*64*128];
__device__ float g_hq     [64*64*128];
__device__ float g_attn   [64*64*64];
__device__ float g_asum   [64*64];
__device__ float g_G      [64*64*128];
// Wv2^T as [n=s_out][k=s_in], bf16 hi/lo, rows padded to 136 elems (272B)
__device__ __align__(16) unsigned short g_Whi[128*136];
__device__ __align__(16) unsigned short g_Wlo[128*136];

__device__ __forceinline__ void cp4(float* dst, const float* src, int n, int t) {
    for (int i = t*4; i < n; i += NTHREADS*4)
        *reinterpret_cast<float4*>(dst + i) = *reinterpret_cast<const float4*>(src + i);
}

__device__ __forceinline__ int colidx(int tx, int j) { return j < 4 ? tx*4 + j : 60 + tx*4 + j; }

__device__ __forceinline__ void zero_acc8(float acc[4][8]) {
    #pragma unroll
    for (int i = 0; i < 4; ++i)
        #pragma unroll
        for (int j = 0; j < 8; ++j) acc[i][j] = 0.f;
}

template<int K>
__device__ __forceinline__ void gemm_tile(const float* __restrict__ A, const float* __restrict__ W,
                                          float acc[4][8], int tx, int ty) {
    const int r0 = ty * 4;
    const int ca = tx * 4, cb = 64 + tx * 4;
    #pragma unroll 4
    for (int k = 0; k < K; ++k) {
        float aa[4];
        #pragma unroll
        for (int i = 0; i < 4; ++i) aa[i] = A[(r0 + i) * K + k];
        float4 b0 = *reinterpret_cast<const float4*>(W + k * 128 + ca);
        float4 b1 = *reinterpret_cast<const float4*>(W + k * 128 + cb);
        float bb[8] = {b0.x, b0.y, b0.z, b0.w, b1.x, b1.y, b1.z, b1.w};
        #pragma unroll
        for (int i = 0; i < 4; ++i)
            #pragma unroll
            for (int j = 0; j < 8; ++j)
                acc[i][j] = fmaf(aa[i], bb[j], acc[i][j]);
    }
}

__device__ __forceinline__ void store_row4(float* base, int row, int tx, const float v[8]) {
    *reinterpret_cast<float4*>(base + row * 128 + tx * 4)      = make_float4(v[0], v[1], v[2], v[3]);
    *reinterpret_cast<float4*>(base + row * 128 + 64 + tx * 4) = make_float4(v[4], v[5], v[6], v[7]);
}

__device__ __forceinline__ unsigned smem_u32(const void* p) {
    unsigned a;
    asm("{ .reg .u64 t; cvta.to.shared.u64 t, %1; cvt.u32.u64 %0, t; }" : "=r"(a) : "l"(p));
    return a;
}

#define LDSM_X4(r, addr)                                                       \
    asm volatile("ldmatrix.sync.aligned.m8n8.x4.shared.b16 {%0,%1,%2,%3}, [%4];" \
        : "=r"((r)[0]), "=r"((r)[1]), "=r"((r)[2]), "=r"((r)[3]) : "r"(addr))

#define MMA16816(d, a, b0, b1)                                                 \
    asm volatile("mma.sync.aligned.m16n8k16.row.col.f32.bf16.bf16.f32 "        \
        "{%0,%1,%2,%3}, {%4,%5,%6,%7}, {%8,%9}, {%0,%1,%2,%3};"                \
        : "+f"((d)[0]), "+f"((d)[1]), "+f"((d)[2]), "+f"((d)[3])               \
        : "r"((a)[0]), "r"((a)[1]), "r"((a)[2]), "r"((a)[3]), "r"(b0), "r"(b1))

#define GBAR(gid)                                                              \
    asm volatile("bar.sync %0, %1;" :: "r"(gid), "r"(256u) : "memory")

// =====================================================================
// Kernel kW: precompute Wv2^T bf16 hi/lo into padded [128][136]. grid 64
// =====================================================================
__global__ __launch_bounds__(256) void kW(Params P) {
    int t = blockIdx.x * 256 + threadIdx.x;
    const float* Wv2 = P.p[14];
    if (t < 16384) {
        int n = t >> 7, k = t & 127;
        float v = Wv2[k * 128 + n];
        __nv_bfloat16 hb = __float2bfloat16(v);
        __nv_bfloat16 lb = __float2bfloat16(v - __bfloat162float(hb));
        g_Whi[n * 136 + k] = __bfloat16_as_ushort(hb);
        g_Wlo[n * 136 + k] = __bfloat16_as_ushort(lb);
    }
}

// =====================================================================
// Kernel A1: keys / queries MLPs + hk, hq projections. grid (64 bc, 2 paths)
// =====================================================================
__global__ __launch_bounds__(256) void kA1(Params P) {
    extern __shared__ float sm[];
    float* X  = sm;
    float* W  = sm + 6144;
    float* T1 = W + 16384;
    float* T2 = T1 + 8192;
    const int t = threadIdx.x, tx = t & 15, ty = t >> 4;
    const int bc = blockIdx.x;
    const int r0 = ty * 4;
    float acc[4][8];

    if (blockIdx.y == 0) {
        cp4(X, P.p[0] + bc * 6144, 6144, t);
        cp4(W, P.p[2], 12288, t);
        __syncthreads();
        zero_acc8(acc);
        gemm_tile<96>(X, W, acc, tx, ty);
        {
            const float aK = P.p[18][0];
            const float* bk1 = P.p[3];
            #pragma unroll
            for (int i = 0; i < 4; ++i) {
                float v[8];
                #pragma unroll
                for (int j = 0; j < 8; ++j) {
                    int c = colidx(tx, j);
                    float x = acc[i][j] + bk1[c];
                    v[j] = x >= 0.f ? x : aK * x;
                }
                store_row4(T1, r0 + i, tx, v);
            }
        }
        __syncthreads();
        cp4(W, P.p[4], 16384, t);
        __syncthreads();
        zero_acc8(acc);
        gemm_tile<128>(T1, W, acc, tx, ty);
        {
            const float* bk2 = P.p[5];
            const float* gK  = P.p[20];
            const float* beK = P.p[21];
            #pragma unroll
            for (int i = 0; i < 4; ++i) {
                float v[8]; float s1 = 0.f, s2 = 0.f;
                #pragma unroll
                for (int j = 0; j < 8; ++j) {
                    int c = colidx(tx, j);
                    float x = tanhf(acc[i][j] + bk2[c]);
                    v[j] = x; s1 += x; s2 += x * x;
                }
                #pragma unroll
                for (int off = 8; off >= 1; off >>= 1) {
                    s1 += __shfl_xor_sync(0xffffffffu, s1, off);
                    s2 += __shfl_xor_sync(0xffffffffu, s2, off);
                }
                float m  = s1 * (1.f / 128.f);
                float va = s2 * (1.f / 128.f) - m * m;
                float rs = rsqrtf(va + 1e-5f);
                #pragma unroll
                for (int j = 0; j < 8; ++j) {
                    int c = colidx(tx, j);
                    v[j] = (v[j] - m) * rs * gK[c] + beK[c];
                }
                store_row4(T2, r0 + i, tx, v);
            }
        }
        __syncthreads();
        cp4(W, P.p[6], 16384, t);
        __syncthreads();
        zero_acc8(acc);
        gemm_tile<128>(T2, W, acc, tx, ty);
        {
            const float* bk3 = P.p[7];
            float* kout = g_keys + bc * 8192;
            #pragma unroll
            for (int i = 0; i < 4; ++i) {
                float v[8];
                #pragma unroll
                for (int j = 0; j < 8; ++j) v[j] = acc[i][j] + bk3[colidx(tx, j)];
                store_row4(T1, r0 + i, tx, v);
                store_row4(kout, r0 + i, tx, v);
            }
        }
        __syncthreads();
        cp4(W, P.p[12] + 16384, 16384, t);
        __syncthreads();
        zero_acc8(acc);
        gemm_tile<128>(T1, W, acc, tx, ty);
        {
            float* hkout = g_hk + bc * 8192;
            #pragma unroll
            for (int i = 0; i < 4; ++i) {
                float v[8];
                #pragma unroll
                for (int j = 0; j < 8; ++j) v[j] = acc[i][j];
                store_row4(hkout, r0 + i, tx, v);
            }
        }
    } else {
        cp4(X, P.p[1] + bc * 6144, 6144, t);
        cp4(W, P.p[8], 12288, t);
        __syncthreads();
        zero_acc8(acc);
        gemm_tile<96>(X, W, acc, tx, ty);
        {
            const float* bq1 = P.p[9];
            #pragma unroll
            for (int i = 0; i < 4; ++i) {
                float v[8];
                #pragma unroll
                for (int j = 0; j < 8; ++j) v[j] = tanhf(acc[i][j] + bq1[colidx(tx, j)]);
                store_row4(T1, r0 + i, tx, v);
            }
        }
        __syncthreads();
        cp4(W, P.p[10], 16384, t);
        __syncthreads();
        zero_acc8(acc);
        gemm_tile<128>(T1, W, acc, tx, ty);
        {
            const float* bq2 = P.p[11];
            float* qout = g_queries + bc * 8192;
            #pragma unroll
            for (int i = 0; i < 4; ++i) {
                float v[8];
                #pragma unroll
                for (int j = 0; j < 8; ++j) v[j] = acc[i][j] + bq2[colidx(tx, j)];
                store_row4(T2, r0 + i, tx, v);
                store_row4(qout, r0 + i, tx, v);
            }
        }
        __syncthreads();
        cp4(W, P.p[12], 16384, t);
        __syncthreads();
        zero_acc8(acc);
        gemm_tile<128>(T2, W, acc, tx, ty);
        {
            float* hqout = g_hq + bc * 8192;
            #pragma unroll
            for (int i = 0; i < 4; ++i) {
                float v[8];
                #pragma unroll
                for (int j = 0; j < 8; ++j) v[j] = acc[i][j];
                store_row4(hqout, r0 + i, tx, v);
            }
        }
    }
}

// =====================================================================
// Kernel A2: logits + softmax over n (axis 2) + attn row sums. grid 64
// =====================================================================
__global__ __launch_bounds__(256) void kA2(Params P) {
    extern __shared__ float sm[];
    float* Kp = sm;
    float* Q  = sm + 8256;
    float* L  = Q + 8256;
    const int t = threadIdx.x, tx = t & 15, ty = t >> 4;
    const int bc = blockIdx.x;

    for (int i = t; i < 8192; i += NTHREADS) {
        int r = i >> 7, c = i & 127;
        Kp[r * 129 + c] = g_keys[bc * 8192 + i];
        Q [r * 129 + c] = g_queries[bc * 8192 + i];
    }
    __syncthreads();

    float acc[4][4];
    #pragma unroll
    for (int i = 0; i < 4; ++i)
        #pragma unroll
        for (int j = 0; j < 4; ++j) acc[i][j] = 0.f;
    #pragma unroll 4
    for (int k = 0; k < 128; ++k) {
        float a[4], b[4];
        #pragma unroll
        for (int i = 0; i < 4; ++i) a[i] = Kp[(ty * 4 + i) * 129 + k];
        #pragma unroll
        for (int j = 0; j < 4; ++j) b[j] = Q[(tx * 4 + j) * 129 + k];
        #pragma unroll
        for (int i = 0; i < 4; ++i)
            #pragma unroll
            for (int j = 0; j < 4; ++j) acc[i][j] = fmaf(a[i], b[j], acc[i][j]);
    }
    #pragma unroll
    for (int i = 0; i < 4; ++i)
        #pragma unroll
        for (int j = 0; j < 4; ++j) L[(ty * 4 + i) * 65 + tx * 4 + j] = acc[i][j];
    __syncthreads();

    if (t < 64) {
        int m = t;
        float mx = -1e30f;
        for (int n = 0; n < 64; ++n) mx = fmaxf(mx, L[n * 65 + m]);
        float s = 0.f;
        for (int n = 0; n < 64; ++n) { float e = expf(L[n * 65 + m] - mx); L[n * 65 + m] = e; s += e; }
        float inv = 1.f / s;
        for (int n = 0; n < 64; ++n) L[n * 65 + m] *= inv;
    }
    __syncthreads();
    if (t < 64) {
        int n = t; float s = 0.f;
        for (int m = 0; m < 64; ++m) {
            float v = L[n * 65 + m];
            g_attn[bc * 4096 + n * 64 + m] = v;
            s += v;
        }
        g_asum[bc * 64 + n] = s;
    }
}

// =====================================================================
// Kernel B (persistent, dual-group HMMA, 32x64 warp tiles): grid 148x512.
// Two 8-warp groups share W hi/lo (loaded once); each group = 4 M-warps
// x 2 N-warps over a 128x128 tile; loops over (bc, n-pair) items.
// =====================================================================
// byte offsets within dynamic smem
#define KB_WHI    0u
#define KB_WLO    34816u
#define KB_A      69632u           // + group*69632: Ahi; Alo = +34816
#define KB_CONST  208896u          // bv1s, bv2s, gvs, bevs (128 floats each)
#define KB_GRP    210944u          // + group*5632: arow(512B) hkn(1024B) red(2048B) s1h(1024B) s2h(1024B)
#define KB_SMEM_BYTES 222208

__global__ __launch_bounds__(512, 1) void kB(Params P) {
    extern __shared__ char smc[];
    const int t = threadIdx.x;
    const int wid = t >> 5, l = t & 31;
    const int group = wid >> 3;         // 0 or 1
    const int gt = t & 255;             // thread within group
    const int gw = wid & 7;             // warp within group
    const int gid = group + 1;          // named barrier id
    const int mwarp = gw & 3, nwarp = gw >> 2;

    float* bv1s = reinterpret_cast<float*>(smc + KB_CONST);
    float* bv2s = bv1s + 128;
    float* gvs  = bv2s + 128;
    float* bevs = gvs + 128;
    char* grp  = smc + KB_GRP + group * 5632u;
    float* arow = reinterpret_cast<float*>(grp);   // 128
    float* hkn  = arow + 128;                      // 256
    float* red  = hkn + 256;                       // 8 warps x 64
    float* s1h  = red + 512;                       // 2 x 128
    float* s2h  = s1h + 256;                       // 2 x 128

    unsigned short* Ahi = reinterpret_cast<unsigned short*>(smc + KB_A + group * 69632u);
    unsigned short* Alo = reinterpret_cast<unsigned short*>(reinterpret_cast<char*>(Ahi) + 34816);

    // ---- one-time staging: W hi/lo + const vectors (all 512 threads) ----
    {
        const float4* s0 = reinterpret_cast<const float4*>(g_Whi);
        const float4* s1 = reinterpret_cast<const float4*>(g_Wlo);
        float4* d0 = reinterpret_cast<float4*>(smc + KB_WHI);
        float4* d1 = reinterpret_cast<float4*>(smc + KB_WLO);
        for (int i = t; i < 2176; i += 512) { d0[i] = s0[i]; d1[i] = s1[i]; }
        if (t < 128) {
            bv1s[t] = P.p[13][t];
            bv2s[t] = P.p[15][t];
            gvs[t]  = P.p[22][t];
            bevs[t] = P.p[23][t];
        }
    }
    __syncthreads();

    const float aV = P.p[19][0];
    const unsigned sbase = smem_u32(smc);
    // A: 32-row strip at mwarp*32; two 16-row ldmatrix bases
    const unsigned aAddr0 = sbase + KB_A + group * 69632u
                          + ((mwarp * 32 + (l & 15)) * 136) * 2 + (l >> 4) * 16;
    const unsigned aAddr1 = aAddr0 + 16 * 272;
    // B: 64-col strip at nwarp*64; p in 0..3 steps 16 cols (4352 B)
    const unsigned bRow = (l & 7) + ((l >> 4) & 1) * 8;
    const unsigned bAddr = sbase + KB_WHI + ((nwarp * 64 + bRow) * 136) * 2 + ((l >> 3) & 1) * 16;

    for (int item = blockIdx.x * 2 + group; item < 2048; item += 296) {
        const int bc = item >> 5;
        const int n0 = (item & 31) * 2;

        // ---- per-item staging ----
        if (gt < 128) arow[gt] = g_attn[bc * 4096 + n0 * 64 + gt];
        hkn[gt] = g_hk[(bc * 64 + n0) * 128 + gt];
        GBAR(gid);

        // ---- build A tile (rows = n_l*64+m, cols = k), bf16 hi/lo ----
        {
            const int r = gt >> 1, ac = gt & 1;
            const int m = r & 63, nl = r >> 6;
            const float* hq = g_hq + bc * 8192 + m * 128 + ac * 64;
            const float* hk = hkn + nl * 128 + ac * 64;
            const float* bv = bv1s + ac * 64;
            unsigned short* ph = Ahi + r * 136 + ac * 64;
            unsigned short* pl = Alo + r * 136 + ac * 64;
            #pragma unroll 4
            for (int j = 0; j < 16; ++j) {
                float4 h  = *reinterpret_cast<const float4*>(hq + j * 4);
                float4 kk = *reinterpret_cast<const float4*>(hk + j * 4);
                float4 bb = *reinterpret_cast<const float4*>(bv + j * 4);
                float a0 = h.x + kk.x + bb.x; a0 = a0 >= 0.f ? a0 : aV * a0;
                float a1 = h.y + kk.y + bb.y; a1 = a1 >= 0.f ? a1 : aV * a1;
                float a2 = h.z + kk.z + bb.z; a2 = a2 >= 0.f ? a2 : aV * a2;
                float a3 = h.w + kk.w + bb.w; a3 = a3 >= 0.f ? a3 : aV * a3;
                __nv_bfloat16 h0 = __float2bfloat16(a0), h1 = __float2bfloat16(a1);
                __nv_bfloat16 h2 = __float2bfloat16(a2), h3 = __float2bfloat16(a3);
                __nv_bfloat16 l0 = __float2bfloat16(a0 - __bfloat162float(h0));
                __nv_bfloat16 l1 = __float2bfloat16(a1 - __bfloat162float(h1));
                __nv_bfloat16 l2 = __float2bfloat16(a2 - __bfloat162float(h2));
                __nv_bfloat16 l3 = __float2bfloat16(a3 - __bfloat162float(h3));
                ushort4 vh, vl;
                vh.x = __bfloat16_as_ushort(h0); vh.y = __bfloat16_as_ushort(h1);
                vh.z = __bfloat16_as_ushort(h2); vh.w = __bfloat16_as_ushort(h3);
                vl.x = __bfloat16_as_ushort(l0); vl.y = __bfloat16_as_ushort(l1);
                vl.z = __bfloat16_as_ushort(l2); vl.w = __bfloat16_as_ushort(l3);
                *reinterpret_cast<ushort4*>(ph + j * 4) = vh;
                *reinterpret_cast<ushort4*>(pl + j * 4) = vl;
            }
        }
        GBAR(gid);

        // ---- GEMM: warp = 32m x 64n, K=128, 3 chains ----
        float acc[2][8][4];
        #pragma unroll
        for (int mt = 0; mt < 2; ++mt)
            #pragma unroll
            for (int nt = 0; nt < 8; ++nt)
                #pragma unroll
                for (int j = 0; j < 4; ++j) acc[mt][nt][j] = 0.f;

        #pragma unroll
        for (int ks = 0; ks < 8; ++ks) {
            unsigned ah0[4], ah1[4], al0[4], al1[4];
            LDSM_X4(ah0, aAddr0 + ks * 32);
            LDSM_X4(ah1, aAddr1 + ks * 32);
            LDSM_X4(al0, aAddr0 + 34816 + ks * 32);
            LDSM_X4(al1, aAddr1 + 34816 + ks * 32);
            #pragma unroll
            for (int p = 0; p < 4; ++p) {
                unsigned bh[4], bl[4];
                LDSM_X4(bh, bAddr + p * 4352 + ks * 32);
                LDSM_X4(bl, bAddr + 34816 + p * 4352 + ks * 32);
                MMA16816(acc[0][2*p],     ah0, bh[0], bh[1]);
                MMA16816(acc[0][2*p + 1], ah0, bh[2], bh[3]);
                MMA16816(acc[1][2*p],     ah1, bh[0], bh[1]);
                MMA16816(acc[1][2*p + 1], ah1, bh[2], bh[3]);
                MMA16816(acc[0][2*p],     ah0, bl[0], bl[1]);
                MMA16816(acc[0][2*p + 1], ah0, bl[2], bl[3]);
                MMA16816(acc[1][2*p],     ah1, bl[0], bl[1]);
                MMA16816(acc[1][2*p + 1], ah1, bl[2], bl[3]);
                MMA16816(acc[0][2*p],     al0, bh[0], bh[1]);
                MMA16816(acc[0][2*p + 1], al0, bh[2], bh[3]);
                MMA16816(acc[1][2*p],     al1, bh[0], bh[1]);
                MMA16816(acc[1][2*p + 1], al1, bh[2], bh[3]);
            }
        }

        // ---- epilogue: tanh + partial row stats (64 cols per warp) ----
        const int qr = l >> 2, qc = l & 3;
        #pragma unroll
        for (int mt = 0; mt < 2; ++mt) {
            float sa1 = 0.f, sa2 = 0.f, sb1 = 0.f, sb2 = 0.f;
            #pragma unroll
            for (int nt = 0; nt < 8; ++nt) {
                int c0 = nwarp * 64 + nt * 8 + qc * 2;
                float x0 = tanhf(acc[mt][nt][0] + bv2s[c0]);
                float x1 = tanhf(acc[mt][nt][1] + bv2s[c0 + 1]);
                float x2 = tanhf(acc[mt][nt][2] + bv2s[c0]);
                float x3 = tanhf(acc[mt][nt][3] + bv2s[c0 + 1]);
                acc[mt][nt][0] = x0; acc[mt][nt][1] = x1;
                acc[mt][nt][2] = x2; acc[mt][nt][3] = x3;
                sa1 += x0 + x1; sa2 += x0 * x0 + x1 * x1;
                sb1 += x2 + x3; sb2 += x2 * x2 + x3 * x3;
            }
            #pragma unroll
            for (int off = 1; off <= 2; off <<= 1) {
                sa1 += __shfl_xor_sync(0xffffffffu, sa1, off);
                sa2 += __shfl_xor_sync(0xffffffffu, sa2, off);
                sb1 += __shfl_xor_sync(0xffffffffu, sb1, off);
                sb2 += __shfl_xor_sync(0xffffffffu, sb2, off);
            }
            if (qc == 0) {
                int ra = mwarp * 32 + mt * 16 + qr;
                s1h[nwarp * 128 + ra]     = sa1;
                s2h[nwarp * 128 + ra]     = sa2;
                s1h[nwarp * 128 + ra + 8] = sb1;
                s2h[nwarp * 128 + ra + 8] = sb2;
            }
        }
        GBAR(gid);

        // ---- per-row LN coefs + weighted column partials ----
        {
            float aco[2][2], bsum = 0.f, ws = 0.f;
            #pragma unroll
            for (int mt = 0; mt < 2; ++mt)
                #pragma unroll
                for (int hh = 0; hh < 2; ++hh) {
                    int row = mwarp * 32 + mt * 16 + qr + hh * 8;
                    float ts1 = s1h[row] + s1h[128 + row];
                    float ts2 = s2h[row] + s2h[128 + row];
                    float mu = ts1 * (1.f / 128.f);
                    float rs = rsqrtf(ts2 * (1.f / 128.f) - mu * mu + 1e-5f);
                    float w = arow[row];
                    float a = w * rs;
                    aco[mt][hh] = a;
                    bsum += a * mu;
                    ws += w;
                }

            float part[16];
            #pragma unroll
            for (int nt = 0; nt < 8; ++nt) {
                #pragma unroll
                for (int jj = 0; jj < 2; ++jj) {
                    int c = nwarp * 64 + nt * 8 + qc * 2 + jj;
                    float inner = aco[0][0] * acc[0][nt][jj]
                                + aco[0][1] * acc[0][nt][jj + 2]
                                + aco[1][0] * acc[1][nt][jj]
                                + aco[1][1] * acc[1][nt][jj + 2]
                                - bsum;
                    part[nt * 2 + jj] = gvs[c] * inner + bevs[c] * ws;
                }
            }
            #pragma unroll
            for (int off = 4; off <= 16; off <<= 1)
                #pragma unroll
                for (int s = 0; s < 16; ++s)
                    part[s] += __shfl_xor_sync(0xffffffffu, part[s], off);
            if (l < 4) {
                #pragma unroll
                for (int nt = 0; nt < 8; ++nt) {
                    red[gw * 64 + nt * 8 + l * 2 + 0] = part[nt * 2 + 0];
                    red[gw * 64 + nt * 8 + l * 2 + 1] = part[nt * 2 + 1];
                }
            }
        }
        GBAR(gid);

        // ---- final: sum the two m-warps per (n, col-half), store g_G ----
        {
            const int nl = gt >> 7, c = gt & 127;
            const int nh = c >> 6, cl = c & 63;
            const int w0 = nl * 2 + nh * 4;
            g_G[(bc * 64 + n0 + nl) * 128 + c] = red[w0 * 64 + cl] + red[(w0 + 1) * 64 + cl];
        }
        GBAR(gid);
    }
}

// =====================================================================
// Kernel C: out = g @ Wv3 + asum * bv3. grid (64, 2) column halves
// =====================================================================
__global__ __launch_bounds__(256) void kC(Params P, float* __restrict__ out) {
    extern __shared__ float sm[];
    float* A = sm;          // 8192
    float* W = sm + 8192;   // 8192 (128 x 64 half)
    const int t = threadIdx.x, tx = t & 15, ty = t >> 4;
    const int bc = blockIdx.x, half = blockIdx.y;
    const int r0 = ty * 4;

    cp4(A, g_G + bc * 8192, 8192, t);
    {
        const float* Wv3 = P.p[16];
        for (int i = t; i < 8192; i += NTHREADS) {
            int k = i >> 6, c = i & 63;
            W[i] = Wv3[k * 128 + half * 64 + c];
        }
    }
    __syncthreads();

    float acc[4][4];
    #pragma unroll
    for (int i = 0; i < 4; ++i)
        #pragma unroll
        for (int j = 0; j < 4; ++j) acc[i][j] = 0.f;
    #pragma unroll 4
    for (int k = 0; k < 128; ++k) {
        float a[4];
        #pragma unroll
        for (int i = 0; i < 4; ++i) a[i] = A[(r0 + i) * 128 + k];
        float4 b4 = *reinterpret_cast<const float4*>(W + k * 64 + tx * 4);
        float bb[4] = {b4.x, b4.y, b4.z, b4.w};
        #pragma unroll
        for (int i = 0; i < 4; ++i)
            #pragma unroll
            for (int j = 0; j < 4; ++j)
                acc[i][j] = fmaf(a[i], bb[j], acc[i][j]);
    }

    const float* bv3 = P.p[17];
    #pragma unroll
    for (int i = 0; i < 4; ++i) {
        int r = r0 + i;
        float as = g_asum[bc * 64 + r];
        float4 v;
        int cb = half * 64 + tx * 4;
        v.x = acc[i][0] + as * bv3[cb + 0];
        v.y = acc[i][1] + as * bv3[cb + 1];
        v.z = acc[i][2] + as * bv3[cb + 2];
        v.w = acc[i][3] + as * bv3[cb + 3];
        *reinterpret_cast<float4*>(out + (bc * 64 + r) * 128 + cb) = v;
    }
}

// =====================================================================
extern "C" void kernel_launch(void* const* d_in, const int* in_sizes, int n_in,
                              void* d_out, int out_size) {
    (void)in_sizes; (void)n_in; (void)out_size;
    Params P;
    for (int i = 0; i < 24; ++i) P.p[i] = reinterpret_cast<const float*>(d_in[i]);

    const int SMEM_A1 = (6144 + 16384 + 8192 + 8192) * 4;
    const int SMEM_A2 = (8256 + 8256 + 64 * 65) * 4;
    const int SMEM_B  = KB_SMEM_BYTES;
    const int SMEM_C  = (8192 + 8192) * 4;

    cudaFuncSetAttribute(kA1, cudaFuncAttributeMaxDynamicSharedMemorySize, SMEM_A1);
    cudaFuncSetAttribute(kA2, cudaFuncAttributeMaxDynamicSharedMemorySize, SMEM_A2);
    cudaFuncSetAttribute(kB,  cudaFuncAttributeMaxDynamicSharedMemorySize, SMEM_B);
    cudaFuncSetAttribute(kC,  cudaFuncAttributeMaxDynamicSharedMemorySize, SMEM_C);

    kW <<<64, 256>>>(P);
    kA1<<<dim3(64, 2), NTHREADS, SMEM_A1>>>(P);
    kA2<<<64, NTHREADS, SMEM_A2>>>(P);
    kB <<<148, 512, SMEM_B>>>(P);
    kC <<<dim3(64, 2), NTHREADS, SMEM_C>>>(P, reinterpret_cast<float*>(d_out));
}

// round 7
// speedup vs baseline: 1.1138x; 1.1138x over previous
#include <cuda_runtime.h>
#include <cuda_bf16.h>

#define NTHREADS 256

struct Params { const float* p[24]; };

// ---- scratch (static device globals; no allocation) ----
__device__ float g_keys   [64*64*128];
__device__ float g_queries[64*64*128];
__device__ float g_hk     [64*64*128];
__device__ float g_hq     [64*64*128];
__device__ float g_attn   [64*64*64];
__device__ float g_asum   [64*64];
__device__ float g_G      [64*64*128];
// Wv2^T as [n=s_out][k=s_in], bf16 hi/lo, rows padded to 136 elems (272B)
__device__ __align__(16) unsigned short g_Whi[128*136];
__device__ __align__(16) unsigned short g_Wlo[128*136];

__device__ __forceinline__ float tanha(float x) {
    float y;
    asm("tanh.approx.f32 %0, %1;" : "=f"(y) : "f"(x));
    return y;
}

__device__ __forceinline__ void cp4(float* dst, const float* src, int n, int t) {
    for (int i = t*4; i < n; i += NTHREADS*4)
        *reinterpret_cast<float4*>(dst + i) = *reinterpret_cast<const float4*>(src + i);
}

__device__ __forceinline__ int colidx(int tx, int j) { return j < 4 ? tx*4 + j : 60 + tx*4 + j; }

__device__ __forceinline__ void zero_acc8(float acc[4][8]) {
    #pragma unroll
    for (int i = 0; i < 4; ++i)
        #pragma unroll
        for (int j = 0; j < 8; ++j) acc[i][j] = 0.f;
}

template<int K>
__device__ __forceinline__ void gemm_tile(const float* __restrict__ A, const float* __restrict__ W,
                                          float acc[4][8], int tx, int ty) {
    const int r0 = ty * 4;
    const int ca = tx * 4, cb = 64 + tx * 4;
    #pragma unroll 4
    for (int k = 0; k < K; ++k) {
        float aa[4];
        #pragma unroll
        for (int i = 0; i < 4; ++i) aa[i] = A[(r0 + i) * K + k];
        float4 b0 = *reinterpret_cast<const float4*>(W + k * 128 + ca);
        float4 b1 = *reinterpret_cast<const float4*>(W + k * 128 + cb);
        float bb[8] = {b0.x, b0.y, b0.z, b0.w, b1.x, b1.y, b1.z, b1.w};
        #pragma unroll
        for (int i = 0; i < 4; ++i)
            #pragma unroll
            for (int j = 0; j < 8; ++j)
                acc[i][j] = fmaf(aa[i], bb[j], acc[i][j]);
    }
}

__device__ __forceinline__ void store_row4(float* base, int row, int tx, const float v[8]) {
    *reinterpret_cast<float4*>(base + row * 128 + tx * 4)      = make_float4(v[0], v[1], v[2], v[3]);
    *reinterpret_cast<float4*>(base + row * 128 + 64 + tx * 4) = make_float4(v[4], v[5], v[6], v[7]);
}

__device__ __forceinline__ unsigned smem_u32(const void* p) {
    unsigned a;
    asm("{ .reg .u64 t; cvta.to.shared.u64 t, %1; cvt.u32.u64 %0, t; }" : "=r"(a) : "l"(p));
    return a;
}

#define LDSM_X4(r, addr)                                                       \
    asm volatile("ldmatrix.sync.aligned.m8n8.x4.shared.b16 {%0,%1,%2,%3}, [%4];" \
        : "=r"((r)[0]), "=r"((r)[1]), "=r"((r)[2]), "=r"((r)[3]) : "r"(addr))

#define MMA16816(d, a, b0, b1)                                                 \
    asm volatile("mma.sync.aligned.m16n8k16.row.col.f32.bf16.bf16.f32 "        \
        "{%0,%1,%2,%3}, {%4,%5,%6,%7}, {%8,%9}, {%0,%1,%2,%3};"                \
        : "+f"((d)[0]), "+f"((d)[1]), "+f"((d)[2]), "+f"((d)[3])               \
        : "r"((a)[0]), "r"((a)[1]), "r"((a)[2]), "r"((a)[3]), "r"(b0), "r"(b1))

#define GBAR(gid)                                                              \
    asm volatile("bar.sync %0, %1;" :: "r"(gid), "r"(256u) : "memory")

// =====================================================================
// Kernel kW: precompute Wv2^T bf16 hi/lo into padded [128][136]. grid 64
// =====================================================================
__global__ __launch_bounds__(256) void kW(Params P) {
    int t = blockIdx.x * 256 + threadIdx.x;
    const float* Wv2 = P.p[14];
    if (t < 16384) {
        int n = t >> 7, k = t & 127;
        float v = Wv2[k * 128 + n];
        __nv_bfloat16 hb = __float2bfloat16(v);
        __nv_bfloat16 lb = __float2bfloat16(v - __bfloat162float(hb));
        g_Whi[n * 136 + k] = __bfloat16_as_ushort(hb);
        g_Wlo[n * 136 + k] = __bfloat16_as_ushort(lb);
    }
}

// =====================================================================
// Kernel A1: keys / queries MLPs + hk, hq projections. grid (64 bc, 2 paths)
// =====================================================================
__global__ __launch_bounds__(256) void kA1(Params P) {
    extern __shared__ float sm[];
    float* X  = sm;
    float* W  = sm + 6144;
    float* T1 = W + 16384;
    float* T2 = T1 + 8192;
    const int t = threadIdx.x, tx = t & 15, ty = t >> 4;
    const int bc = blockIdx.x;
    const int r0 = ty * 4;
    float acc[4][8];

    if (blockIdx.y == 0) {
        cp4(X, P.p[0] + bc * 6144, 6144, t);
        cp4(W, P.p[2], 12288, t);
        __syncthreads();
        zero_acc8(acc);
        gemm_tile<96>(X, W, acc, tx, ty);
        {
            const float aK = P.p[18][0];
            const float* bk1 = P.p[3];
            #pragma unroll
            for (int i = 0; i < 4; ++i) {
                float v[8];
                #pragma unroll
                for (int j = 0; j < 8; ++j) {
                    int c = colidx(tx, j);
                    float x = acc[i][j] + bk1[c];
                    v[j] = x >= 0.f ? x : aK * x;
                }
                store_row4(T1, r0 + i, tx, v);
            }
        }
        __syncthreads();
        cp4(W, P.p[4], 16384, t);
        __syncthreads();
        zero_acc8(acc);
        gemm_tile<128>(T1, W, acc, tx, ty);
        {
            const float* bk2 = P.p[5];
            const float* gK  = P.p[20];
            const float* beK = P.p[21];
            #pragma unroll
            for (int i = 0; i < 4; ++i) {
                float v[8]; float s1 = 0.f, s2 = 0.f;
                #pragma unroll
                for (int j = 0; j < 8; ++j) {
                    int c = colidx(tx, j);
                    float x = tanha(acc[i][j] + bk2[c]);
                    v[j] = x; s1 += x; s2 += x * x;
                }
                #pragma unroll
                for (int off = 8; off >= 1; off >>= 1) {
                    s1 += __shfl_xor_sync(0xffffffffu, s1, off);
                    s2 += __shfl_xor_sync(0xffffffffu, s2, off);
                }
                float m  = s1 * (1.f / 128.f);
                float va = s2 * (1.f / 128.f) - m * m;
                float rs = rsqrtf(va + 1e-5f);
                #pragma unroll
                for (int j = 0; j < 8; ++j) {
                    int c = colidx(tx, j);
                    v[j] = (v[j] - m) * rs * gK[c] + beK[c];
                }
                store_row4(T2, r0 + i, tx, v);
            }
        }
        __syncthreads();
        cp4(W, P.p[6], 16384, t);
        __syncthreads();
        zero_acc8(acc);
        gemm_tile<128>(T2, W, acc, tx, ty);
        {
            const float* bk3 = P.p[7];
            float* kout = g_keys + bc * 8192;
            #pragma unroll
            for (int i = 0; i < 4; ++i) {
                float v[8];
                #pragma unroll
                for (int j = 0; j < 8; ++j) v[j] = acc[i][j] + bk3[colidx(tx, j)];
                store_row4(T1, r0 + i, tx, v);
                store_row4(kout, r0 + i, tx, v);
            }
        }
        __syncthreads();
        cp4(W, P.p[12] + 16384, 16384, t);
        __syncthreads();
        zero_acc8(acc);
        gemm_tile<128>(T1, W, acc, tx, ty);
        {
            float* hkout = g_hk + bc * 8192;
            #pragma unroll
            for (int i = 0; i < 4; ++i) {
                float v[8];
                #pragma unroll
                for (int j = 0; j < 8; ++j) v[j] = acc[i][j];
                store_row4(hkout, r0 + i, tx, v);
            }
        }
    } else {
        cp4(X, P.p[1] + bc * 6144, 6144, t);
        cp4(W, P.p[8], 12288, t);
        __syncthreads();
        zero_acc8(acc);
        gemm_tile<96>(X, W, acc, tx, ty);
        {
            const float* bq1 = P.p[9];
            #pragma unroll
            for (int i = 0; i < 4; ++i) {
                float v[8];
                #pragma unroll
                for (int j = 0; j < 8; ++j) v[j] = tanha(acc[i][j] + bq1[colidx(tx, j)]);
                store_row4(T1, r0 + i, tx, v);
            }
        }
        __syncthreads();
        cp4(W, P.p[10], 16384, t);
        __syncthreads();
        zero_acc8(acc);
        gemm_tile<128>(T1, W, acc, tx, ty);
        {
            const float* bq2 = P.p[11];
            float* qout = g_queries + bc * 8192;
            #pragma unroll
            for (int i = 0; i < 4; ++i) {
                float v[8];
                #pragma unroll
                for (int j = 0; j < 8; ++j) v[j] = acc[i][j] + bq2[colidx(tx, j)];
                store_row4(T2, r0 + i, tx, v);
                store_row4(qout, r0 + i, tx, v);
            }
        }
        __syncthreads();
        cp4(W, P.p[12], 16384, t);
        __syncthreads();
        zero_acc8(acc);
        gemm_tile<128>(T2, W, acc, tx, ty);
        {
            float* hqout = g_hq + bc * 8192;
            #pragma unroll
            for (int i = 0; i < 4; ++i) {
                float v[8];
                #pragma unroll
                for (int j = 0; j < 8; ++j) v[j] = acc[i][j];
                store_row4(hqout, r0 + i, tx, v);
            }
        }
    }
}

// =====================================================================
// Kernel A2: logits + softmax over n (axis 2) + attn row sums. grid 64
// =====================================================================
__global__ __launch_bounds__(256) void kA2(Params P) {
    extern __shared__ float sm[];
    float* Kp = sm;
    float* Q  = sm + 8256;
    float* L  = Q + 8256;
    const int t = threadIdx.x, tx = t & 15, ty = t >> 4;
    const int bc = blockIdx.x;

    for (int i = t; i < 8192; i += NTHREADS) {
        int r = i >> 7, c = i & 127;
        Kp[r * 129 + c] = g_keys[bc * 8192 + i];
        Q [r * 129 + c] = g_queries[bc * 8192 + i];
    }
    __syncthreads();

    float acc[4][4];
    #pragma unroll
    for (int i = 0; i < 4; ++i)
        #pragma unroll
        for (int j = 0; j < 4; ++j) acc[i][j] = 0.f;
    #pragma unroll 4
    for (int k = 0; k < 128; ++k) {
        float a[4], b[4];
        #pragma unroll
        for (int i = 0; i < 4; ++i) a[i] = Kp[(ty * 4 + i) * 129 + k];
        #pragma unroll
        for (int j = 0; j < 4; ++j) b[j] = Q[(tx * 4 + j) * 129 + k];
        #pragma unroll
        for (int i = 0; i < 4; ++i)
            #pragma unroll
            for (int j = 0; j < 4; ++j) acc[i][j] = fmaf(a[i], b[j], acc[i][j]);
    }
    #pragma unroll
    for (int i = 0; i < 4; ++i)
        #pragma unroll
        for (int j = 0; j < 4; ++j) L[(ty * 4 + i) * 65 + tx * 4 + j] = acc[i][j];
    __syncthreads();

    if (t < 64) {
        int m = t;
        float mx = -1e30f;
        for (int n = 0; n < 64; ++n) mx = fmaxf(mx, L[n * 65 + m]);
        float s = 0.f;
        for (int n = 0; n < 64; ++n) { float e = expf(L[n * 65 + m] - mx); L[n * 65 + m] = e; s += e; }
        float inv = 1.f / s;
        for (int n = 0; n < 64; ++n) L[n * 65 + m] *= inv;
    }
    __syncthreads();
    if (t < 64) {
        int n = t; float s = 0.f;
        for (int m = 0; m < 64; ++m) {
            float v = L[n * 65 + m];
            g_attn[bc * 4096 + n * 64 + m] = v;
            s += v;
        }
        g_asum[bc * 64 + n] = s;
    }
}

// =====================================================================
// Kernel B (persistent, dual-group HMMA): grid 148 x 512 threads.
// Two 8-warp groups share W hi/lo in smem (loaded once), each loops over
// (bc, n-pair) items with its own A buffers + named barrier.
// R4 layout (16x128 warp tiles) + tanh.approx epilogue.
// =====================================================================
// byte offsets within dynamic smem
#define KB_WHI    0u
#define KB_WLO    34816u
#define KB_A      69632u           // + group*69632: Ahi; Alo = +34816
#define KB_CONST  208896u          // bv1s, bv2s, gvs, bevs (128 floats each)
#define KB_GRP    210944u          // + group*5632: arow(512B) hkn(1024B) red(4096B)
#define KB_SMEM_BYTES 222208

__global__ __launch_bounds__(512, 1) void kB(Params P) {
    extern __shared__ char smc[];
    const int t = threadIdx.x;
    const int wid = t >> 5, l = t & 31;
    const int group = wid >> 3;         // 0 or 1
    const int gt = t & 255;             // thread within group
    const int gw = wid & 7;             // warp within group
    const int gid = group + 1;          // named barrier id

    float* bv1s = reinterpret_cast<float*>(smc + KB_CONST);
    float* bv2s = bv1s + 128;
    float* gvs  = bv2s + 128;
    float* bevs = gvs + 128;
    char* grp  = smc + KB_GRP + group * 5632u;
    float* arow = reinterpret_cast<float*>(grp);
    float* hkn  = arow + 128;
    float* red  = hkn + 256;            // 8 warps x 128

    unsigned short* Ahi = reinterpret_cast<unsigned short*>(smc + KB_A + group * 69632u);
    unsigned short* Alo = reinterpret_cast<unsigned short*>(reinterpret_cast<char*>(Ahi) + 34816);

    // ---- one-time staging: W hi/lo + const vectors (all 512 threads) ----
    {
        const float4* s0 = reinterpret_cast<const float4*>(g_Whi);
        const float4* s1 = reinterpret_cast<const float4*>(g_Wlo);
        float4* d0 = reinterpret_cast<float4*>(smc + KB_WHI);
        float4* d1 = reinterpret_cast<float4*>(smc + KB_WLO);
        for (int i = t; i < 2176; i += 512) { d0[i] = s0[i]; d1[i] = s1[i]; }
        if (t < 128) {
            bv1s[t] = P.p[13][t];
            bv2s[t] = P.p[15][t];
            gvs[t]  = P.p[22][t];
            bevs[t] = P.p[23][t];
        }
    }
    __syncthreads();

    const float aV = P.p[19][0];
    const unsigned sbase = smem_u32(smc);
    const unsigned aHiAddr = sbase + KB_A + group * 69632u
                           + ((gw * 16 + (l & 15)) * 136) * 2 + (l >> 4) * 16;
    const unsigned aLoAddr = aHiAddr + 34816;
    const unsigned bRow = (l & 7) + ((l >> 4) & 1) * 8;
    const unsigned bHiAddr = sbase + KB_WHI + (bRow * 136) * 2 + ((l >> 3) & 1) * 16;
    const unsigned bLoAddr = bHiAddr + 34816;

    for (int item = blockIdx.x * 2 + group; item < 2048; item += 296) {
        const int bc = item >> 5;
        const int n0 = (item & 31) * 2;

        // ---- per-item staging ----
        if (gt < 128) arow[gt] = g_attn[bc * 4096 + n0 * 64 + gt];
        hkn[gt] = g_hk[(bc * 64 + n0) * 128 + gt];
        GBAR(gid);

        // ---- build A tile (rows = n_l*64+m, cols = k), bf16 hi/lo ----
        {
            const int r = gt >> 1, ac = gt & 1;
            const int m = r & 63, nl = r >> 6;
            const float* hq = g_hq + bc * 8192 + m * 128 + ac * 64;
            const float* hk = hkn + nl * 128 + ac * 64;
            const float* bv = bv1s + ac * 64;
            unsigned short* ph = Ahi + r * 136 + ac * 64;
            unsigned short* pl = Alo + r * 136 + ac * 64;
            #pragma unroll 4
            for (int j = 0; j < 16; ++j) {
                float4 h  = *reinterpret_cast<const float4*>(hq + j * 4);
                float4 kk = *reinterpret_cast<const float4*>(hk + j * 4);
                float4 bb = *reinterpret_cast<const float4*>(bv + j * 4);
                float a0 = h.x + kk.x + bb.x; a0 = a0 >= 0.f ? a0 : aV * a0;
                float a1 = h.y + kk.y + bb.y; a1 = a1 >= 0.f ? a1 : aV * a1;
                float a2 = h.z + kk.z + bb.z; a2 = a2 >= 0.f ? a2 : aV * a2;
                float a3 = h.w + kk.w + bb.w; a3 = a3 >= 0.f ? a3 : aV * a3;
                __nv_bfloat16 h0 = __float2bfloat16(a0), h1 = __float2bfloat16(a1);
                __nv_bfloat16 h2 = __float2bfloat16(a2), h3 = __float2bfloat16(a3);
                __nv_bfloat16 l0 = __float2bfloat16(a0 - __bfloat162float(h0));
                __nv_bfloat16 l1 = __float2bfloat16(a1 - __bfloat162float(h1));
                __nv_bfloat16 l2 = __float2bfloat16(a2 - __bfloat162float(h2));
                __nv_bfloat16 l3 = __float2bfloat16(a3 - __bfloat162float(h3));
                ushort4 vh, vl;
                vh.x = __bfloat16_as_ushort(h0); vh.y = __bfloat16_as_ushort(h1);
                vh.z = __bfloat16_as_ushort(h2); vh.w = __bfloat16_as_ushort(h3);
                vl.x = __bfloat16_as_ushort(l0); vl.y = __bfloat16_as_ushort(l1);
                vl.z = __bfloat16_as_ushort(l2); vl.w = __bfloat16_as_ushort(l3);
                *reinterpret_cast<ushort4*>(ph + j * 4) = vh;
                *reinterpret_cast<ushort4*>(pl + j * 4) = vl;
            }
        }
        GBAR(gid);

        // ---- GEMM: 8 warps x (16m x 128n), K=128, 3 chains ----
        float acc[16][4];
        #pragma unroll
        for (int nt = 0; nt < 16; ++nt)
            #pragma unroll
            for (int j = 0; j < 4; ++j) acc[nt][j] = 0.f;

        #pragma unroll
        for (int ks = 0; ks < 8; ++ks) {
            unsigned ah[4], al[4];
            LDSM_X4(ah, aHiAddr + ks * 32);
            LDSM_X4(al, aLoAddr + ks * 32);
            #pragma unroll
            for (int p = 0; p < 8; ++p) {
                unsigned bh[4], bl[4];
                LDSM_X4(bh, bHiAddr + p * 4352 + ks * 32);
                LDSM_X4(bl, bLoAddr + p * 4352 + ks * 32);
                MMA16816(acc[2*p],     ah, bh[0], bh[1]);
                MMA16816(acc[2*p + 1], ah, bh[2], bh[3]);
                MMA16816(acc[2*p],     ah, bl[0], bl[1]);
                MMA16816(acc[2*p + 1], ah, bl[2], bl[3]);
                MMA16816(acc[2*p],     al, bh[0], bh[1]);
                MMA16816(acc[2*p + 1], al, bh[2], bh[3]);
            }
        }

        // ---- epilogue: tanh.approx + LN + attn-weighted reduce over m ----
        {
            const int qr = l >> 2, qc = l & 3;
            const int r0 = gw * 16 + qr, r1 = r0 + 8;
            float s1a = 0.f, s2a = 0.f, s1b = 0.f, s2b = 0.f;
            #pragma unroll
            for (int nt = 0; nt < 16; ++nt) {
                int c0 = nt * 8 + qc * 2;
                float x0 = tanha(acc[nt][0] + bv2s[c0]);
                float x1 = tanha(acc[nt][1] + bv2s[c0 + 1]);
                float x2 = tanha(acc[nt][2] + bv2s[c0]);
                float x3 = tanha(acc[nt][3] + bv2s[c0 + 1]);
                acc[nt][0] = x0; acc[nt][1] = x1; acc[nt][2] = x2; acc[nt][3] = x3;
                s1a += x0 + x1; s2a += x0 * x0 + x1 * x1;
                s1b += x2 + x3; s2b += x2 * x2 + x3 * x3;
            }
            #pragma unroll
            for (int off = 1; off <= 2; off <<= 1) {
                s1a += __shfl_xor_sync(0xffffffffu, s1a, off);
                s2a += __shfl_xor_sync(0xffffffffu, s2a, off);
                s1b += __shfl_xor_sync(0xffffffffu, s1b, off);
                s2b += __shfl_xor_sync(0xffffffffu, s2b, off);
            }
            float mua = s1a * (1.f / 128.f);
            float rsa = rsqrtf(s2a * (1.f / 128.f) - mua * mua + 1e-5f);
            float mub = s1b * (1.f / 128.f);
            float rsb = rsqrtf(s2b * (1.f / 128.f) - mub * mub + 1e-5f);
            float wa = arow[r0], wb = arow[r1];

            float part[32];
            #pragma unroll
            for (int nt = 0; nt < 16; ++nt) {
                #pragma unroll
                for (int jj = 0; jj < 2; ++jj) {
                    int c = nt * 8 + qc * 2 + jj;
                    float oa = (acc[nt][jj]     - mua) * rsa * gvs[c] + bevs[c];
                    float ob = (acc[nt][jj + 2] - mub) * rsb * gvs[c] + bevs[c];
                    part[nt * 2 + jj] = wa * oa + wb * ob;
                }
            }
            #pragma unroll
            for (int off = 4; off <= 16; off <<= 1)
                #pragma unroll
                for (int s = 0; s < 32; ++s)
                    part[s] += __shfl_xor_sync(0xffffffffu, part[s], off);
            if (l < 4) {
                #pragma unroll
                for (int nt = 0; nt < 16; ++nt) {
                    red[gw * 128 + nt * 8 + l * 2 + 0] = part[nt * 2 + 0];
                    red[gw * 128 + nt * 8 + l * 2 + 1] = part[nt * 2 + 1];
                }
            }
        }
        GBAR(gid);

        {
            const int nl = gt >> 7, c = gt & 127;
            const float* rb = red + nl * 512 + c;
            g_G[(bc * 64 + n0 + nl) * 128 + c] = rb[0] + rb[128] + rb[256] + rb[384];
        }
        GBAR(gid);
    }
}

// =====================================================================
// Kernel C: out = g @ Wv3 + asum * bv3. grid (64, 2) column halves
// =====================================================================
__global__ __launch_bounds__(256) void kC(Params P, float* __restrict__ out) {
    extern __shared__ float sm[];
    float* A = sm;          // 8192
    float* W = sm + 8192;   // 8192 (128 x 64 half)
    const int t = threadIdx.x, tx = t & 15, ty = t >> 4;
    const int bc = blockIdx.x, half = blockIdx.y;
    const int r0 = ty * 4;

    cp4(A, g_G + bc * 8192, 8192, t);
    {
        const float* Wv3 = P.p[16];
        for (int i = t; i < 8192; i += NTHREADS) {
            int k = i >> 6, c = i & 63;
            W[i] = Wv3[k * 128 + half * 64 + c];
        }
    }
    __syncthreads();

    float acc[4][4];
    #pragma unroll
    for (int i = 0; i < 4; ++i)
        #pragma unroll
        for (int j = 0; j < 4; ++j) acc[i][j] = 0.f;
    #pragma unroll 4
    for (int k = 0; k < 128; ++k) {
        float a[4];
        #pragma unroll
        for (int i = 0; i < 4; ++i) a[i] = A[(r0 + i) * 128 + k];
        float4 b4 = *reinterpret_cast<const float4*>(W + k * 64 + tx * 4);
        float bb[4] = {b4.x, b4.y, b4.z, b4.w};
        #pragma unroll
        for (int i = 0; i < 4; ++i)
            #pragma unroll
            for (int j = 0; j < 4; ++j)
                acc[i][j] = fmaf(a[i], bb[j], acc[i][j]);
    }

    const float* bv3 = P.p[17];
    #pragma unroll
    for (int i = 0; i < 4; ++i) {
        int r = r0 + i;
        float as = g_asum[bc * 64 + r];
        float4 v;
        int cb = half * 64 + tx * 4;
        v.x = acc[i][0] + as * bv3[cb + 0];
        v.y = acc[i][1] + as * bv3[cb + 1];
        v.z = acc[i][2] + as * bv3[cb + 2];
        v.w = acc[i][3] + as * bv3[cb + 3];
        *reinterpret_cast<float4*>(out + (bc * 64 + r) * 128 + cb) = v;
    }
}

// =====================================================================
extern "C" void kernel_launch(void* const* d_in, const int* in_sizes, int n_in,
                              void* d_out, int out_size) {
    (void)in_sizes; (void)n_in; (void)out_size;
    Params P;
    for (int i = 0; i < 24; ++i) P.p[i] = reinterpret_cast<const float*>(d_in[i]);

    const int SMEM_A1 = (6144 + 16384 + 8192 + 8192) * 4;
    const int SMEM_A2 = (8256 + 8256 + 64 * 65) * 4;
    const int SMEM_B  = KB_SMEM_BYTES;
    const int SMEM_C  = (8192 + 8192) * 4;

    cudaFuncSetAttribute(kA1, cudaFuncAttributeMaxDynamicSharedMemorySize, SMEM_A1);
    cudaFuncSetAttribute(kA2, cudaFuncAttributeMaxDynamicSharedMemorySize, SMEM_A2);
    cudaFuncSetAttribute(kB,  cudaFuncAttributeMaxDynamicSharedMemorySize, SMEM_B);
    cudaFuncSetAttribute(kC,  cudaFuncAttributeMaxDynamicSharedMemorySize, SMEM_C);

    kW <<<64, 256>>>(P);
    kA1<<<dim3(64, 2), NTHREADS, SMEM_A1>>>(P);
    kA2<<<64, NTHREADS, SMEM_A2>>>(P);
    kB <<<148, 512, SMEM_B>>>(P);
    kC <<<dim3(64, 2), NTHREADS, SMEM_C>>>(P, reinterpret_cast<float*>(d_out));
}